// round 1
// baseline (speedup 1.0000x reference)
#include <cuda_runtime.h>
#include <math.h>

// ---- model constants ----
#define Bq   32
#define IMGS 128
#define Dm   512
#define NH   8
#define NL   8
#define MLPD 2048
#define NP   256
#define NT   257
#define HDm  64

// ---- scratch (device globals; no allocation allowed) ----
__device__ float g_comb[Bq * NP * 2 * Dm];   // [src_tok | orig_tok]
__device__ float g_gate[Bq * NP * Dm];
__device__ float g_tok [Bq * NT * Dm];
__device__ float g_x   [Bq * NT * Dm];
__device__ float g_qkv [Bq * NT * 3 * Dm];
__device__ float g_o   [Bq * NT * Dm];
__device__ float g_h   [Bq * NT * MLPD];

// ============================================================
// SPT: shifted-patch tokenization (both weight sets) + LayerNorm
// One block per (b, patch). 512 threads = one per output channel.
// ============================================================
__device__ __forceinline__ float ln512(float a, float* red, int tid) {
    red[tid] = a; __syncthreads();
    for (int s = 256; s > 0; s >>= 1) { if (tid < s) red[tid] += red[tid + s]; __syncthreads(); }
    float mu = red[0] * (1.f / 512.f); __syncthreads();
    float dv = a - mu;
    red[tid] = dv * dv; __syncthreads();
    for (int s = 256; s > 0; s >>= 1) { if (tid < s) red[tid] += red[tid + s]; __syncthreads(); }
    float var = red[0] * (1.f / 512.f); __syncthreads();
    return dv * rsqrtf(var + 1e-5f);
}

__global__ void spt_kernel(const float* __restrict__ img,
    const float* __restrict__ w0, const float* __restrict__ bb0,
    const float* __restrict__ gg0, const float* __restrict__ be0,
    const float* __restrict__ w1, const float* __restrict__ bb1,
    const float* __restrict__ gg1, const float* __restrict__ be1,
    float* __restrict__ comb)
{
    int blk = blockIdx.x;
    int b = blk >> 8;
    int p = blk & 255;
    int py = p >> 4, px = p & 15;

    __shared__ float patch[10][10];
    __shared__ float red[512];
    int tid = threadIdx.x;

    if (tid < 100) {
        int r = tid / 10, c = tid % 10;
        int ir = (py * 8 - 1 + r) & 127;
        int ic = (px * 8 - 1 + c) & 127;
        patch[r][c] = img[((size_t)b * IMGS + ir) * IMGS + ic];
    }
    __syncthreads();

    // shift offsets into the 10x10 window (window row 0 = image row py*8-1)
    const int dy[5] = {1, 0, 2, 0, 2};
    const int dx[5] = {1, 0, 0, 2, 2};

    int d = tid;
    float a0 = bb0[d], a1 = bb1[d];
    const float* wp0 = w0 + (size_t)d * 320;
    const float* wp1 = w1 + (size_t)d * 320;

    for (int c = 0; c < 5; c++) {
        #pragma unroll
        for (int i = 0; i < 8; i++) {
            #pragma unroll
            for (int j = 0; j < 8; j++) {
                float xv = patch[i + dy[c]][j + dx[c]];
                int wi = (c * 8 + i) * 8 + j;
                a0 = fmaf(wp0[wi], xv, a0);
                a1 = fmaf(wp1[wi], xv, a1);
            }
        }
    }

    float n0 = ln512(a0, red, tid) * gg0[d] + be0[d];
    float n1 = ln512(a1, red, tid) * gg1[d] + be1[d];

    size_t row = blk;
    comb[row * 1024 + d]       = n0;   // src_tok
    comb[row * 1024 + 512 + d] = n1;   // orig_tok
}

// ============================================================
// Generic FP32 SGEMM: C = act(A[MxK] @ B[KxN] + bias) (+ residual)
// 64x64 tile, BK=16, 256 threads, 4x4 micro-tile per thread.
// act: 0 none, 1 sigmoid, 2 exact gelu
// ============================================================
__global__ void sgemm_kernel(const float* __restrict__ A, const float* __restrict__ Bm,
                             const float* __restrict__ bias, const float* __restrict__ res,
                             float* __restrict__ C, int M, int Nn, int K, int act)
{
    __shared__ float As[16][65];
    __shared__ float Bs[16][64];
    int tid = threadIdx.x;
    int tx = tid & 15, ty = tid >> 4;
    int m0 = blockIdx.y * 64, n0 = blockIdx.x * 64;

    float acc[4][4] = {};

    for (int k0 = 0; k0 < K; k0 += 16) {
        #pragma unroll
        for (int t = 0; t < 4; t++) {
            int e = tid + t * 256;
            int ar = e >> 4, ac = e & 15;
            int gm = m0 + ar;
            As[ac][ar] = (gm < M) ? A[(size_t)gm * K + k0 + ac] : 0.f;
            int br = e >> 6, bc = e & 63;
            int gn = n0 + bc;
            Bs[br][bc] = (gn < Nn) ? Bm[(size_t)(k0 + br) * Nn + gn] : 0.f;
        }
        __syncthreads();
        #pragma unroll
        for (int kk = 0; kk < 16; kk++) {
            float av[4], bv[4];
            #pragma unroll
            for (int i = 0; i < 4; i++) av[i] = As[kk][ty * 4 + i];
            #pragma unroll
            for (int j = 0; j < 4; j++) bv[j] = Bs[kk][tx * 4 + j];
            #pragma unroll
            for (int i = 0; i < 4; i++)
                #pragma unroll
                for (int j = 0; j < 4; j++)
                    acc[i][j] = fmaf(av[i], bv[j], acc[i][j]);
        }
        __syncthreads();
    }

    #pragma unroll
    for (int i = 0; i < 4; i++) {
        int m = m0 + ty * 4 + i;
        if (m >= M) continue;
        #pragma unroll
        for (int j = 0; j < 4; j++) {
            int n = n0 + tx * 4 + j;
            if (n >= Nn) continue;
            float v = acc[i][j];
            if (bias) v += bias[n];
            if (act == 1)      v = 1.f / (1.f + expf(-v));
            else if (act == 2) v = 0.5f * v * (1.f + erff(v * 0.70710678118654752f));
            if (res) v += res[(size_t)m * Nn + n];
            C[(size_t)m * Nn + n] = v;
        }
    }
}

// ============================================================
// LayerNorm over D=512, one block per row, 128 threads
// ============================================================
__global__ void ln_kernel(const float* __restrict__ in, const float* __restrict__ g,
                          const float* __restrict__ bta, float* __restrict__ out)
{
    int row = blockIdx.x, tid = threadIdx.x;
    __shared__ float red[128];
    const float* xr = in + (size_t)row * Dm;
    float v[4]; float s = 0.f;
    #pragma unroll
    for (int i = 0; i < 4; i++) { v[i] = xr[tid + 128 * i]; s += v[i]; }
    red[tid] = s; __syncthreads();
    for (int st = 64; st > 0; st >>= 1) { if (tid < st) red[tid] += red[tid + st]; __syncthreads(); }
    float mu = red[0] * (1.f / 512.f); __syncthreads();
    float s2 = 0.f;
    #pragma unroll
    for (int i = 0; i < 4; i++) { float dv = v[i] - mu; s2 += dv * dv; }
    red[tid] = s2; __syncthreads();
    for (int st = 64; st > 0; st >>= 1) { if (tid < st) red[tid] += red[tid + st]; __syncthreads(); }
    float inv = rsqrtf(red[0] * (1.f / 512.f) + 1e-5f);
    float* orow = out + (size_t)row * Dm;
    #pragma unroll
    for (int i = 0; i < 4; i++) {
        int idx = tid + 128 * i;
        orow[idx] = (v[i] - mu) * inv * g[idx] + bta[idx];
    }
}

// ============================================================
// Attention: one block per (b, h, n). 128 threads.
// scores -> diag mask -> softmax -> AV, writes o[(b,n), h*64+d]
// ============================================================
__global__ void attn_kernel(const float* __restrict__ qkv, const float* __restrict__ temp,
                            float* __restrict__ o)
{
    int n = blockIdx.x, h = blockIdx.y, b = blockIdx.z;
    int tid = threadIdx.x;
    __shared__ float q[64];
    __shared__ float pr[NT];
    __shared__ float red[128];

    const float* qrow = qkv + ((size_t)(b * NT + n) * 1536) + h * 64;
    if (tid < 64) q[tid] = qrow[tid];
    __syncthreads();

    float tmp = temp[h];
    for (int m = tid; m < NT; m += 128) {
        float s;
        if (m == n) s = -INFINITY;
        else {
            const float* kr = qkv + ((size_t)(b * NT + m) * 1536) + 512 + h * 64;
            float acc = 0.f;
            #pragma unroll
            for (int dd = 0; dd < 64; dd++) acc = fmaf(q[dd], kr[dd], acc);
            s = acc * tmp;
        }
        pr[m] = s;
    }
    __syncthreads();

    float lm = -INFINITY;
    for (int m = tid; m < NT; m += 128) lm = fmaxf(lm, pr[m]);
    red[tid] = lm; __syncthreads();
    for (int st = 64; st > 0; st >>= 1) { if (tid < st) red[tid] = fmaxf(red[tid], red[tid + st]); __syncthreads(); }
    float mx = red[0]; __syncthreads();

    float ls = 0.f;
    for (int m = tid; m < NT; m += 128) { float e = expf(pr[m] - mx); pr[m] = e; ls += e; }
    red[tid] = ls; __syncthreads();
    for (int st = 64; st > 0; st >>= 1) { if (tid < st) red[tid] += red[tid + st]; __syncthreads(); }
    float inv = 1.f / red[0];
    __syncthreads();

    int dd = tid & 63, part = tid >> 6;
    float acc = 0.f;
    for (int m = part; m < NT; m += 2)
        acc = fmaf(pr[m], qkv[((size_t)(b * NT + m) * 1536) + 1024 + h * 64 + dd], acc);
    red[tid] = acc; __syncthreads();
    if (part == 0)
        o[((size_t)(b * NT + n) * Dm) + h * 64 + dd] = (red[tid] + red[tid + 64]) * inv;
}

// ============================================================
// Gate fuse + positional embed; cls row init
// ============================================================
__global__ void fuse_kernel(const float* __restrict__ comb, const float* __restrict__ gate,
                            const float* __restrict__ pos, float* __restrict__ tok)
{
    int idx = blockIdx.x * blockDim.x + threadIdx.x;
    if (idx >= Bq * NP * Dm) return;
    int d = idx & 511;
    int row = idx >> 9;             // b*256 + p
    int b = row >> 8, p = row & 255;
    float g  = gate[idx];
    float sv = comb[(size_t)row * 1024 + d];
    float ov = comb[(size_t)row * 1024 + 512 + d];
    tok[((size_t)(b * NT) + 1 + p) * Dm + d] =
        g * sv + (1.f - g) * ov + pos[(size_t)(1 + p) * Dm + d];
}

__global__ void cls_kernel(const float* __restrict__ cls, const float* __restrict__ pos,
                           float* __restrict__ tok)
{
    int idx = blockIdx.x * blockDim.x + threadIdx.x;
    if (idx >= Bq * Dm) return;
    int d = idx & 511, b = idx >> 9;
    tok[(size_t)b * NT * Dm + d] = cls[d] + pos[d];
}

// ============================================================
// Head: LN(cls token) @ hw + hb. One block per batch element.
// ============================================================
__global__ void head_kernel(const float* __restrict__ tok, const float* __restrict__ ng,
                            const float* __restrict__ nb, const float* __restrict__ hw,
                            const float* __restrict__ hb, float* __restrict__ out)
{
    int b = blockIdx.x, tid = threadIdx.x; // 128
    __shared__ float red[128];
    const float* xr = tok + (size_t)b * NT * Dm;   // cls row
    float v[4]; float s = 0.f;
    #pragma unroll
    for (int i = 0; i < 4; i++) { v[i] = xr[tid + 128 * i]; s += v[i]; }
    red[tid] = s; __syncthreads();
    for (int st = 64; st > 0; st >>= 1) { if (tid < st) red[tid] += red[tid + st]; __syncthreads(); }
    float mu = red[0] * (1.f / 512.f); __syncthreads();
    float s2 = 0.f;
    #pragma unroll
    for (int i = 0; i < 4; i++) { float dv = v[i] - mu; s2 += dv * dv; }
    red[tid] = s2; __syncthreads();
    for (int st = 64; st > 0; st >>= 1) { if (tid < st) red[tid] += red[tid + st]; __syncthreads(); }
    float inv = rsqrtf(red[0] * (1.f / 512.f) + 1e-5f);
    __syncthreads();

    float xn[4];
    #pragma unroll
    for (int i = 0; i < 4; i++) {
        int idx = tid + 128 * i;
        xn[i] = (v[i] - mu) * inv * ng[idx] + nb[idx];
    }

    for (int c = 0; c < 3; c++) {
        float p = 0.f;
        #pragma unroll
        for (int i = 0; i < 4; i++) {
            int idx = tid + 128 * i;
            p = fmaf(xn[i], hw[idx * 3 + c], p);
        }
        red[tid] = p; __syncthreads();
        for (int st = 64; st > 0; st >>= 1) { if (tid < st) red[tid] += red[tid + st]; __syncthreads(); }
        if (tid == 0) out[b * 3 + c] = red[0] + hb[c];
        __syncthreads();
    }
}

// ============================================================
// Launch
// ============================================================
static inline void launch_gemm(const float* A, const float* Bm, const float* bias,
                               const float* res, float* C, int M, int Nn, int K, int act)
{
    dim3 grid((Nn + 63) / 64, (M + 63) / 64);
    sgemm_kernel<<<grid, 256>>>(A, Bm, bias, res, C, M, Nn, K, act);
}

extern "C" void kernel_launch(void* const* d_in, const int* in_sizes, int n_in,
                              void* d_out, int out_size)
{
    const float* image   = (const float*)d_in[0];
    const float* ssw     = (const float*)d_in[1];
    const float* ssb     = (const float*)d_in[2];
    const float* ssg     = (const float*)d_in[3];
    const float* ssbeta  = (const float*)d_in[4];
    const float* sow     = (const float*)d_in[5];
    const float* sob     = (const float*)d_in[6];
    const float* sog     = (const float*)d_in[7];
    const float* sobeta  = (const float*)d_in[8];
    const float* fw      = (const float*)d_in[9];
    const float* fb      = (const float*)d_in[10];
    const float* cls     = (const float*)d_in[11];
    const float* pos     = (const float*)d_in[12];
    const float* ln1g    = (const float*)d_in[13];
    const float* ln1b    = (const float*)d_in[14];
    const float* qkvw    = (const float*)d_in[15];
    const float* qkvb    = (const float*)d_in[16];
    const float* projw   = (const float*)d_in[17];
    const float* projb   = (const float*)d_in[18];
    const float* temp    = (const float*)d_in[19];
    const float* ln2g    = (const float*)d_in[20];
    const float* ln2b    = (const float*)d_in[21];
    const float* w1      = (const float*)d_in[22];
    const float* b1      = (const float*)d_in[23];
    const float* w2      = (const float*)d_in[24];
    const float* b2      = (const float*)d_in[25];
    const float* ng      = (const float*)d_in[26];
    const float* nb      = (const float*)d_in[27];
    const float* hw      = (const float*)d_in[28];
    const float* hb      = (const float*)d_in[29];

    float *comb, *gate, *tok, *x, *qkv, *o, *h;
    cudaGetSymbolAddress((void**)&comb, g_comb);
    cudaGetSymbolAddress((void**)&gate, g_gate);
    cudaGetSymbolAddress((void**)&tok,  g_tok);
    cudaGetSymbolAddress((void**)&x,    g_x);
    cudaGetSymbolAddress((void**)&qkv,  g_qkv);
    cudaGetSymbolAddress((void**)&o,    g_o);
    cudaGetSymbolAddress((void**)&h,    g_h);

    const int Mtok = Bq * NT;   // 8224
    const int Mpat = Bq * NP;   // 8192

    // ---- front end ----
    spt_kernel<<<Mpat, 512>>>(image, ssw, ssb, ssg, ssbeta,
                                     sow, sob, sog, sobeta, comb);
    launch_gemm(comb, fw, fb, nullptr, gate, Mpat, Dm, 2 * Dm, /*sigmoid*/1);
    fuse_kernel<<<(Mpat * Dm + 255) / 256, 256>>>(comb, gate, pos, tok);
    cls_kernel<<<(Bq * Dm + 255) / 256, 256>>>(cls, pos, tok);

    // ---- transformer layers ----
    for (int l = 0; l < NL; l++) {
        ln_kernel<<<Mtok, 128>>>(tok, ln1g + l * Dm, ln1b + l * Dm, x);
        launch_gemm(x, qkvw + (size_t)l * Dm * 3 * Dm, qkvb + l * 3 * Dm,
                    nullptr, qkv, Mtok, 3 * Dm, Dm, 0);
        attn_kernel<<<dim3(NT, NH, Bq), 128>>>(qkv, temp + l * NH, o);
        launch_gemm(o, projw + (size_t)l * Dm * Dm, projb + l * Dm,
                    tok, tok, Mtok, Dm, Dm, 0);
        ln_kernel<<<Mtok, 128>>>(tok, ln2g + l * Dm, ln2b + l * Dm, x);
        launch_gemm(x, w1 + (size_t)l * Dm * MLPD, b1 + l * MLPD,
                    nullptr, h, Mtok, MLPD, Dm, /*gelu*/2);
        launch_gemm(h, w2 + (size_t)l * MLPD * Dm, b2 + l * Dm,
                    tok, tok, Mtok, Dm, MLPD, 0);
    }

    // ---- head ----
    head_kernel<<<Bq, 128>>>(tok, ng, nb, hw, hb, (float*)d_out);
}

// round 2
// speedup vs baseline: 2.6907x; 2.6907x over previous
#include <cuda_runtime.h>
#include <math.h>

// ---- model constants ----
#define Bq   32
#define IMGS 128
#define Dm   512
#define NH   8
#define NL   8
#define MLPD 2048
#define NP   256
#define NT   257
#define HDm  64

// ---- scratch (device globals; no allocation allowed) ----
__device__ float g_comb[Bq * NP * 2 * Dm];   // [src_tok | orig_tok]
__device__ float g_gate[Bq * NP * Dm];
__device__ float g_tok [Bq * NT * Dm];
__device__ float g_x   [Bq * NT * Dm];
__device__ float g_qkv [Bq * NT * 3 * Dm];
__device__ float g_o   [Bq * NT * Dm];
__device__ float g_h   [Bq * NT * MLPD];

// ============================================================
// SPT: shifted-patch tokenization (both weight sets) + LayerNorm
// ============================================================
__device__ __forceinline__ float ln512(float a, float* red, int tid) {
    red[tid] = a; __syncthreads();
    for (int s = 256; s > 0; s >>= 1) { if (tid < s) red[tid] += red[tid + s]; __syncthreads(); }
    float mu = red[0] * (1.f / 512.f); __syncthreads();
    float dv = a - mu;
    red[tid] = dv * dv; __syncthreads();
    for (int s = 256; s > 0; s >>= 1) { if (tid < s) red[tid] += red[tid + s]; __syncthreads(); }
    float var = red[0] * (1.f / 512.f); __syncthreads();
    return dv * rsqrtf(var + 1e-5f);
}

__global__ void spt_kernel(const float* __restrict__ img,
    const float* __restrict__ w0, const float* __restrict__ bb0,
    const float* __restrict__ gg0, const float* __restrict__ be0,
    const float* __restrict__ w1, const float* __restrict__ bb1,
    const float* __restrict__ gg1, const float* __restrict__ be1,
    float* __restrict__ comb)
{
    int blk = blockIdx.x;
    int b = blk >> 8;
    int p = blk & 255;
    int py = p >> 4, px = p & 15;

    __shared__ float patch[10][10];
    __shared__ float red[512];
    int tid = threadIdx.x;

    if (tid < 100) {
        int r = tid / 10, c = tid % 10;
        int ir = (py * 8 - 1 + r) & 127;
        int ic = (px * 8 - 1 + c) & 127;
        patch[r][c] = img[((size_t)b * IMGS + ir) * IMGS + ic];
    }
    __syncthreads();

    const int dy[5] = {1, 0, 2, 0, 2};
    const int dx[5] = {1, 0, 0, 2, 2};

    int d = tid;
    float a0 = bb0[d], a1 = bb1[d];
    const float* wp0 = w0 + (size_t)d * 320;
    const float* wp1 = w1 + (size_t)d * 320;

    for (int c = 0; c < 5; c++) {
        #pragma unroll
        for (int i = 0; i < 8; i++) {
            #pragma unroll
            for (int j = 0; j < 8; j++) {
                float xv = patch[i + dy[c]][j + dx[c]];
                int wi = (c * 8 + i) * 8 + j;
                a0 = fmaf(wp0[wi], xv, a0);
                a1 = fmaf(wp1[wi], xv, a1);
            }
        }
    }

    float n0 = ln512(a0, red, tid) * gg0[d] + be0[d];
    float n1 = ln512(a1, red, tid) * gg1[d] + be1[d];

    size_t row = blk;
    comb[row * 1024 + d]       = n0;
    comb[row * 1024 + 512 + d] = n1;
}

// ============================================================
// FP32 SGEMM: 128x128 block tile, BK=16, 256 threads, 8x8 micro.
// Double-buffered smem, float4 everywhere. Requires N%128==0, K%16==0.
// act: 0 none, 1 sigmoid, 2 exact gelu. Optional residual add.
// ============================================================
__global__ __launch_bounds__(256) void sgemm128(
    const float* __restrict__ A, const float* __restrict__ B,
    const float* __restrict__ bias, const float* __restrict__ res,
    float* __restrict__ C, int M, int N, int K, int act)
{
    __shared__ float As[2][16][128];   // [k][m] transposed
    __shared__ float Bs[2][16][128];   // [k][n]

    int tid = threadIdx.x;
    int tx = tid & 15, ty = tid >> 4;
    int m0 = blockIdx.y * 128, n0 = blockIdx.x * 128;

    int arow = tid >> 2;            // 0..63
    int acol = (tid & 3) * 4;       // 0,4,8,12
    int brow = tid >> 5;            // 0..7
    int bcol = (tid & 31) * 4;      // 0..124

    float acc[8][8] = {};

    const float4 zero4 = make_float4(0.f, 0.f, 0.f, 0.f);

#define LOAD_TILE(KT, BF) do {                                                   \
        int kbase = (KT) * 16;                                                    \
        _Pragma("unroll")                                                         \
        for (int hh = 0; hh < 2; hh++) {                                          \
            int gm = m0 + arow + hh * 64;                                         \
            float4 a = (gm < M) ? *(const float4*)&A[(size_t)gm * K + kbase + acol] : zero4; \
            As[BF][acol + 0][arow + hh * 64] = a.x;                                \
            As[BF][acol + 1][arow + hh * 64] = a.y;                                \
            As[BF][acol + 2][arow + hh * 64] = a.z;                                \
            As[BF][acol + 3][arow + hh * 64] = a.w;                                \
            float4 bb = *(const float4*)&B[(size_t)(kbase + brow + hh * 8) * N + n0 + bcol]; \
            *(float4*)&Bs[BF][brow + hh * 8][bcol] = bb;                           \
        }                                                                          \
    } while (0)

    int ntiles = K >> 4;
    LOAD_TILE(0, 0);
    __syncthreads();

    for (int t = 0; t < ntiles; t++) {
        int cur = t & 1;
        if (t + 1 < ntiles) LOAD_TILE(t + 1, cur ^ 1);
        #pragma unroll
        for (int kk = 0; kk < 16; kk++) {
            float4 a0 = *(const float4*)&As[cur][kk][ty * 4];
            float4 a1 = *(const float4*)&As[cur][kk][ty * 4 + 64];
            float4 b0 = *(const float4*)&Bs[cur][kk][tx * 4];
            float4 b1 = *(const float4*)&Bs[cur][kk][tx * 4 + 64];
            float av[8] = {a0.x, a0.y, a0.z, a0.w, a1.x, a1.y, a1.z, a1.w};
            float bv[8] = {b0.x, b0.y, b0.z, b0.w, b1.x, b1.y, b1.z, b1.w};
            #pragma unroll
            for (int i = 0; i < 8; i++)
                #pragma unroll
                for (int j = 0; j < 8; j++)
                    acc[i][j] = fmaf(av[i], bv[j], acc[i][j]);
        }
        __syncthreads();
    }
#undef LOAD_TILE

    #pragma unroll
    for (int i = 0; i < 8; i++) {
        int m = m0 + ty * 4 + ((i < 4) ? i : (60 + i));   // +64 for upper half
        if (m >= M) continue;
        #pragma unroll
        for (int jh = 0; jh < 2; jh++) {
            int n = n0 + tx * 4 + jh * 64;
            float4 v;
            v.x = acc[i][jh * 4 + 0]; v.y = acc[i][jh * 4 + 1];
            v.z = acc[i][jh * 4 + 2]; v.w = acc[i][jh * 4 + 3];
            if (bias) {
                float4 bb = *(const float4*)&bias[n];
                v.x += bb.x; v.y += bb.y; v.z += bb.z; v.w += bb.w;
            }
            if (act == 1) {
                v.x = 1.f / (1.f + expf(-v.x)); v.y = 1.f / (1.f + expf(-v.y));
                v.z = 1.f / (1.f + expf(-v.z)); v.w = 1.f / (1.f + expf(-v.w));
            } else if (act == 2) {
                v.x = 0.5f * v.x * (1.f + erff(v.x * 0.70710678118654752f));
                v.y = 0.5f * v.y * (1.f + erff(v.y * 0.70710678118654752f));
                v.z = 0.5f * v.z * (1.f + erff(v.z * 0.70710678118654752f));
                v.w = 0.5f * v.w * (1.f + erff(v.w * 0.70710678118654752f));
            }
            if (res) {
                float4 r = *(const float4*)&res[(size_t)m * N + n];
                v.x += r.x; v.y += r.y; v.z += r.z; v.w += r.w;
            }
            *(float4*)&C[(size_t)m * N + n] = v;
        }
    }
}

// ============================================================
// LayerNorm over D=512, one block per row, 128 threads
// ============================================================
__global__ void ln_kernel(const float* __restrict__ in, const float* __restrict__ g,
                          const float* __restrict__ bta, float* __restrict__ out)
{
    int row = blockIdx.x, tid = threadIdx.x;
    __shared__ float red[128];
    const float* xr = in + (size_t)row * Dm;
    float v[4]; float s = 0.f;
    #pragma unroll
    for (int i = 0; i < 4; i++) { v[i] = xr[tid + 128 * i]; s += v[i]; }
    red[tid] = s; __syncthreads();
    for (int st = 64; st > 0; st >>= 1) { if (tid < st) red[tid] += red[tid + st]; __syncthreads(); }
    float mu = red[0] * (1.f / 512.f); __syncthreads();
    float s2 = 0.f;
    #pragma unroll
    for (int i = 0; i < 4; i++) { float dv = v[i] - mu; s2 += dv * dv; }
    red[tid] = s2; __syncthreads();
    for (int st = 64; st > 0; st >>= 1) { if (tid < st) red[tid] += red[tid + st]; __syncthreads(); }
    float inv = rsqrtf(red[0] * (1.f / 512.f) + 1e-5f);
    float* orow = out + (size_t)row * Dm;
    #pragma unroll
    for (int i = 0; i < 4; i++) {
        int idx = tid + 128 * i;
        orow[idx] = (v[i] - mu) * inv * g[idx] + bta[idx];
    }
}

// ============================================================
// Tiled fused attention: block = (qtile of 64, h, b), 256 threads.
// smem: Qs[64d][68q] (transposed), KVs[64][68], Ss[64q][260m]
// ============================================================
#define QTILES 5           // ceil(257/64)
#define SS_LD  260
#define ATTN_SMEM ((64*68 + 64*68 + 64*SS_LD) * 4)

__global__ __launch_bounds__(256) void attn_kernel(
    const float* __restrict__ qkv, const float* __restrict__ temp,
    float* __restrict__ o)
{
    extern __shared__ float sm[];
    float* Qs  = sm;                 // [d][q], ld 68
    float* KVs = sm + 64 * 68;       // K: [d][m]; V: [m][d], ld 68
    float* Ss  = sm + 2 * 64 * 68;   // [q][m], ld 260

    int qt = blockIdx.x, h = blockIdx.y, b = blockIdx.z;
    int tid = threadIdx.x;
    int tx = tid & 15, ty = tid >> 4;

    const size_t base = (size_t)b * NT * 1536 + (size_t)h * 64;

    // ---- load Q tile, transposed ----
    {
        int dth = (tid & 15) * 4;
        #pragma unroll
        for (int pass = 0; pass < 4; pass++) {
            int q = (tid >> 4) + pass * 16;
            int n = qt * 64 + q; if (n > NT - 1) n = NT - 1;
            float4 v = *(const float4*)&qkv[base + (size_t)n * 1536 + dth];
            Qs[(dth + 0) * 68 + q] = v.x;
            Qs[(dth + 1) * 68 + q] = v.y;
            Qs[(dth + 2) * 68 + q] = v.z;
            Qs[(dth + 3) * 68 + q] = v.w;
        }
    }

    float tmp = temp[h];
    int nbase = qt * 64;

    // ---- scores: S = (Q @ K^T) * temp, diag mask ----
    for (int mc = 0; mc < NT; mc += 64) {
        __syncthreads();
        {
            int dth = (tid & 15) * 4;
            #pragma unroll
            for (int pass = 0; pass < 4; pass++) {
                int m = (tid >> 4) + pass * 16;
                int mg = mc + m; if (mg > NT - 1) mg = NT - 1;
                float4 v = *(const float4*)&qkv[base + 512 + (size_t)mg * 1536 + dth];
                KVs[(dth + 0) * 68 + m] = v.x;
                KVs[(dth + 1) * 68 + m] = v.y;
                KVs[(dth + 2) * 68 + m] = v.z;
                KVs[(dth + 3) * 68 + m] = v.w;
            }
        }
        __syncthreads();

        float acc[4][4] = {};
        #pragma unroll
        for (int kk = 0; kk < 64; kk++) {
            float4 a = *(const float4*)&Qs[kk * 68 + ty * 4];
            float4 bb = *(const float4*)&KVs[kk * 68 + tx * 4];
            float av[4] = {a.x, a.y, a.z, a.w};
            float bv[4] = {bb.x, bb.y, bb.z, bb.w};
            #pragma unroll
            for (int i = 0; i < 4; i++)
                #pragma unroll
                for (int j = 0; j < 4; j++)
                    acc[i][j] = fmaf(av[i], bv[j], acc[i][j]);
        }
        #pragma unroll
        for (int i = 0; i < 4; i++) {
            int q = ty * 4 + i;
            int n = nbase + q;
            #pragma unroll
            for (int j = 0; j < 4; j++) {
                int m = mc + tx * 4 + j;
                if (m < NT) {
                    float s = acc[i][j] * tmp;
                    if (m == n) s = -INFINITY;
                    Ss[q * SS_LD + m] = s;
                }
            }
        }
    }
    __syncthreads();

    // ---- softmax: each warp owns 8 rows ----
    {
        int wid = tid >> 5, lane = tid & 31;
        for (int r = 0; r < 8; r++) {
            float* row = Ss + (wid * 8 + r) * SS_LD;
            float mx = -INFINITY;
            for (int m = lane; m < NT; m += 32) mx = fmaxf(mx, row[m]);
            #pragma unroll
            for (int s = 16; s > 0; s >>= 1) mx = fmaxf(mx, __shfl_xor_sync(0xffffffffu, mx, s));
            float sum = 0.f;
            for (int m = lane; m < NT; m += 32) { float e = expf(row[m] - mx); row[m] = e; sum += e; }
            #pragma unroll
            for (int s = 16; s > 0; s >>= 1) sum += __shfl_xor_sync(0xffffffffu, sum, s);
            float inv = 1.f / sum;
            for (int m = lane; m < NT; m += 32) row[m] *= inv;
        }
    }

    // ---- O = P @ V ----
    float acc[4][4] = {};
    for (int mc = 0; mc < NT; mc += 64) {
        __syncthreads();
        {
            int dth = (tid & 15) * 4;
            #pragma unroll
            for (int pass = 0; pass < 4; pass++) {
                int m = (tid >> 4) + pass * 16;
                int mg = mc + m; if (mg > NT - 1) mg = NT - 1;
                float4 v = *(const float4*)&qkv[base + 1024 + (size_t)mg * 1536 + dth];
                *(float4*)&KVs[m * 68 + dth] = v;
            }
        }
        __syncthreads();
        int mlim = NT - mc; if (mlim > 64) mlim = 64;
        for (int mm = 0; mm < mlim; mm++) {
            float4 bb = *(const float4*)&KVs[mm * 68 + tx * 4];
            float bv[4] = {bb.x, bb.y, bb.z, bb.w};
            #pragma unroll
            for (int i = 0; i < 4; i++) {
                float p = Ss[(ty * 4 + i) * SS_LD + mc + mm];
                #pragma unroll
                for (int j = 0; j < 4; j++)
                    acc[i][j] = fmaf(p, bv[j], acc[i][j]);
            }
        }
    }

    #pragma unroll
    for (int i = 0; i < 4; i++) {
        int n = nbase + ty * 4 + i;
        if (n < NT) {
            float4 v;
            v.x = acc[i][0]; v.y = acc[i][1]; v.z = acc[i][2]; v.w = acc[i][3];
            *(float4*)&o[((size_t)(b * NT + n)) * Dm + h * 64 + tx * 4] = v;
        }
    }
}

// ============================================================
// Gate fuse + positional embed; cls row init
// ============================================================
__global__ void fuse_kernel(const float* __restrict__ comb, const float* __restrict__ gate,
                            const float* __restrict__ pos, float* __restrict__ tok)
{
    int idx = blockIdx.x * blockDim.x + threadIdx.x;
    if (idx >= Bq * NP * Dm) return;
    int d = idx & 511;
    int row = idx >> 9;
    int b = row >> 8, p = row & 255;
    float g  = gate[idx];
    float sv = comb[(size_t)row * 1024 + d];
    float ov = comb[(size_t)row * 1024 + 512 + d];
    tok[((size_t)(b * NT) + 1 + p) * Dm + d] =
        g * sv + (1.f - g) * ov + pos[(size_t)(1 + p) * Dm + d];
}

__global__ void cls_kernel(const float* __restrict__ cls, const float* __restrict__ pos,
                           float* __restrict__ tok)
{
    int idx = blockIdx.x * blockDim.x + threadIdx.x;
    if (idx >= Bq * Dm) return;
    int d = idx & 511, b = idx >> 9;
    tok[(size_t)b * NT * Dm + d] = cls[d] + pos[d];
}

// ============================================================
// Head: LN(cls token) @ hw + hb
// ============================================================
__global__ void head_kernel(const float* __restrict__ tok, const float* __restrict__ ng,
                            const float* __restrict__ nb, const float* __restrict__ hw,
                            const float* __restrict__ hb, float* __restrict__ out)
{
    int b = blockIdx.x, tid = threadIdx.x;
    __shared__ float red[128];
    const float* xr = tok + (size_t)b * NT * Dm;
    float v[4]; float s = 0.f;
    #pragma unroll
    for (int i = 0; i < 4; i++) { v[i] = xr[tid + 128 * i]; s += v[i]; }
    red[tid] = s; __syncthreads();
    for (int st = 64; st > 0; st >>= 1) { if (tid < st) red[tid] += red[tid + st]; __syncthreads(); }
    float mu = red[0] * (1.f / 512.f); __syncthreads();
    float s2 = 0.f;
    #pragma unroll
    for (int i = 0; i < 4; i++) { float dv = v[i] - mu; s2 += dv * dv; }
    red[tid] = s2; __syncthreads();
    for (int st = 64; st > 0; st >>= 1) { if (tid < st) red[tid] += red[tid + st]; __syncthreads(); }
    float inv = rsqrtf(red[0] * (1.f / 512.f) + 1e-5f);
    __syncthreads();

    float xn[4];
    #pragma unroll
    for (int i = 0; i < 4; i++) {
        int idx = tid + 128 * i;
        xn[i] = (v[i] - mu) * inv * ng[idx] + nb[idx];
    }

    for (int c = 0; c < 3; c++) {
        float p = 0.f;
        #pragma unroll
        for (int i = 0; i < 4; i++) {
            int idx = tid + 128 * i;
            p = fmaf(xn[i], hw[idx * 3 + c], p);
        }
        red[tid] = p; __syncthreads();
        for (int st = 64; st > 0; st >>= 1) { if (tid < st) red[tid] += red[tid + st]; __syncthreads(); }
        if (tid == 0) out[b * 3 + c] = red[0] + hb[c];
        __syncthreads();
    }
}

// ============================================================
// Launch
// ============================================================
static inline void launch_gemm(const float* A, const float* Bm, const float* bias,
                               const float* res, float* C, int M, int Nn, int K, int act)
{
    dim3 grid(Nn / 128, (M + 127) / 128);
    sgemm128<<<grid, 256>>>(A, Bm, bias, res, C, M, Nn, K, act);
}

extern "C" void kernel_launch(void* const* d_in, const int* in_sizes, int n_in,
                              void* d_out, int out_size)
{
    const float* image   = (const float*)d_in[0];
    const float* ssw     = (const float*)d_in[1];
    const float* ssb     = (const float*)d_in[2];
    const float* ssg     = (const float*)d_in[3];
    const float* ssbeta  = (const float*)d_in[4];
    const float* sow     = (const float*)d_in[5];
    const float* sob     = (const float*)d_in[6];
    const float* sog     = (const float*)d_in[7];
    const float* sobeta  = (const float*)d_in[8];
    const float* fw      = (const float*)d_in[9];
    const float* fb      = (const float*)d_in[10];
    const float* cls     = (const float*)d_in[11];
    const float* pos     = (const float*)d_in[12];
    const float* ln1g    = (const float*)d_in[13];
    const float* ln1b    = (const float*)d_in[14];
    const float* qkvw    = (const float*)d_in[15];
    const float* qkvb    = (const float*)d_in[16];
    const float* projw   = (const float*)d_in[17];
    const float* projb   = (const float*)d_in[18];
    const float* temp    = (const float*)d_in[19];
    const float* ln2g    = (const float*)d_in[20];
    const float* ln2b    = (const float*)d_in[21];
    const float* w1      = (const float*)d_in[22];
    const float* b1      = (const float*)d_in[23];
    const float* w2      = (const float*)d_in[24];
    const float* b2      = (const float*)d_in[25];
    const float* ng      = (const float*)d_in[26];
    const float* nb      = (const float*)d_in[27];
    const float* hw      = (const float*)d_in[28];
    const float* hb      = (const float*)d_in[29];

    float *comb, *gate, *tok, *x, *qkv, *o, *h;
    cudaGetSymbolAddress((void**)&comb, g_comb);
    cudaGetSymbolAddress((void**)&gate, g_gate);
    cudaGetSymbolAddress((void**)&tok,  g_tok);
    cudaGetSymbolAddress((void**)&x,    g_x);
    cudaGetSymbolAddress((void**)&qkv,  g_qkv);
    cudaGetSymbolAddress((void**)&o,    g_o);
    cudaGetSymbolAddress((void**)&h,    g_h);

    static int attn_smem_set = 0;
    if (!attn_smem_set) {
        cudaFuncSetAttribute(attn_kernel, cudaFuncAttributeMaxDynamicSharedMemorySize, ATTN_SMEM);
        attn_smem_set = 1;
    }

    const int Mtok = Bq * NT;   // 8224
    const int Mpat = Bq * NP;   // 8192

    // ---- front end ----
    spt_kernel<<<Mpat, 512>>>(image, ssw, ssb, ssg, ssbeta,
                              sow, sob, sog, sobeta, comb);
    launch_gemm(comb, fw, fb, nullptr, gate, Mpat, Dm, 2 * Dm, /*sigmoid*/1);
    fuse_kernel<<<(Mpat * Dm + 255) / 256, 256>>>(comb, gate, pos, tok);
    cls_kernel<<<(Bq * Dm + 255) / 256, 256>>>(cls, pos, tok);

    // ---- transformer layers ----
    for (int l = 0; l < NL; l++) {
        ln_kernel<<<Mtok, 128>>>(tok, ln1g + l * Dm, ln1b + l * Dm, x);
        launch_gemm(x, qkvw + (size_t)l * Dm * 3 * Dm, qkvb + l * 3 * Dm,
                    nullptr, qkv, Mtok, 3 * Dm, Dm, 0);
        attn_kernel<<<dim3(QTILES, NH, Bq), 256, ATTN_SMEM>>>(qkv, temp + l * NH, o);
        launch_gemm(o, projw + (size_t)l * Dm * Dm, projb + l * Dm,
                    tok, tok, Mtok, Dm, Dm, 0);
        ln_kernel<<<Mtok, 128>>>(tok, ln2g + l * Dm, ln2b + l * Dm, x);
        launch_gemm(x, w1 + (size_t)l * Dm * MLPD, b1 + l * MLPD,
                    nullptr, h, Mtok, MLPD, Dm, /*gelu*/2);
        launch_gemm(h, w2 + (size_t)l * MLPD * Dm, b2 + l * Dm,
                    tok, tok, Mtok, Dm, MLPD, 0);
    }

    // ---- head ----
    head_kernel<<<Bq, 128>>>(tok, ng, nb, hw, hb, (float*)d_out);
}

// round 5
// speedup vs baseline: 2.9049x; 1.0796x over previous
#include <cuda_runtime.h>
#include <math.h>
#include <stdint.h>

// ---- model constants ----
#define Bq   32
#define IMGS 128
#define Dm   512
#define NH   8
#define NL   8
#define MLPD 2048
#define NP   256
#define NT   257
#define HDm  64

// ---- scratch (device globals; no allocation allowed) ----
__device__ float g_comb[Bq * NP * 2 * Dm];
__device__ float g_gate[Bq * NP * Dm];
__device__ float g_tok [Bq * NT * Dm];
__device__ float g_x   [Bq * NT * Dm];
__device__ float g_qkv [Bq * NT * 3 * Dm];
__device__ float g_o   [Bq * NT * Dm];
__device__ float g_h   [Bq * NT * MLPD];
// transposed (full fp32) weights
__device__ float g_wT  [512*1024 + NL * (1536*512 + 512*512 + 2048*512 + 512*2048)];

#define FWT_OFF   0
#define LAYER_OFF(l) (512*1024 + (size_t)(l) * 3145728)
#define QKVT_OFF  0
#define PROJT_OFF 786432
#define W1T_OFF   1048576
#define W2T_OFF   2097152

__device__ __forceinline__ uint32_t f2tf32(float f) {
    uint32_t u; asm("cvt.rna.tf32.f32 %0, %1;" : "=r"(u) : "f"(f)); return u;
}
// split v into tf32 hi + tf32 lo (3xTF32 scheme)
__device__ __forceinline__ void tf32_split(float v, uint32_t& hi, uint32_t& lo) {
    hi = f2tf32(v);
    lo = f2tf32(v - __uint_as_float(hi));
}

__device__ __forceinline__ void mma8(float c[4], const uint32_t a[4], const uint32_t b[2]) {
    asm volatile(
        "mma.sync.aligned.m16n8k8.row.col.f32.tf32.tf32.f32 "
        "{%0,%1,%2,%3}, {%4,%5,%6,%7}, {%8,%9}, {%0,%1,%2,%3};"
        : "+f"(c[0]), "+f"(c[1]), "+f"(c[2]), "+f"(c[3])
        : "r"(a[0]), "r"(a[1]), "r"(a[2]), "r"(a[3]), "r"(b[0]), "r"(b[1]));
}

// ============================================================
// 3xTF32 tensor-core GEMM: C[M,N] = act(A[M,K] @ BT[N,K]^T + bias) (+res)
// CTA tile 128x128, BK=16, 256 threads = 8 warps (4M x 2N),
// warp tile 32x64 via m16n8k8. Requires N%128==0, K%16==0.
// act: 0 none, 1 sigmoid, 2 exact gelu.
// ============================================================
__global__ __launch_bounds__(256) void mma_gemm(
    const float* __restrict__ A, const float* __restrict__ BT,
    const float* __restrict__ bias, const float* __restrict__ res,
    float* __restrict__ C, int M, int N, int K, int act)
{
    __shared__ float As[2][128][20];
    __shared__ float Bs[2][128][20];

    int tid = threadIdx.x;
    int wid = tid >> 5, lane = tid & 31;
    int g = lane >> 2, tig = lane & 3;
    int m0 = blockIdx.y * 128, n0 = blockIdx.x * 128;
    int wm = (wid & 3) * 32, wn = (wid >> 2) * 64;

    float c[2][8][4] = {};

#define LOADT(T, BUF) do {                                                       \
        int kb = (T) * 16;                                                        \
        _Pragma("unroll")                                                         \
        for (int i = 0; i < 2; i++) {                                             \
            int e = tid + i * 256;                                                \
            int r = e >> 2, cc = (e & 3) * 4;                                     \
            int gm = m0 + r; if (gm > M - 1) gm = M - 1;                          \
            float4 va = *(const float4*)&A[(size_t)gm * K + kb + cc];             \
            *(float4*)&As[BUF][r][cc] = va;                                       \
            float4 vb = *(const float4*)&BT[(size_t)(n0 + r) * K + kb + cc];      \
            *(float4*)&Bs[BUF][r][cc] = vb;                                       \
        }                                                                          \
    } while (0)

    int ntiles = K >> 4;
    LOADT(0, 0);
    __syncthreads();

    for (int t = 0; t < ntiles; t++) {
        int cur = t & 1;
        if (t + 1 < ntiles) LOADT(t + 1, cur ^ 1);

        #pragma unroll
        for (int kk = 0; kk < 16; kk += 8) {
            uint32_t afh[2][4], afl[2][4];
            #pragma unroll
            for (int mf = 0; mf < 2; mf++) {
                int r = wm + mf * 16 + g;
                tf32_split(As[cur][r    ][kk + tig    ], afh[mf][0], afl[mf][0]);
                tf32_split(As[cur][r + 8][kk + tig    ], afh[mf][1], afl[mf][1]);
                tf32_split(As[cur][r    ][kk + tig + 4], afh[mf][2], afl[mf][2]);
                tf32_split(As[cur][r + 8][kk + tig + 4], afh[mf][3], afl[mf][3]);
            }
            uint32_t bfh[8][2], bfl[8][2];
            #pragma unroll
            for (int nf = 0; nf < 8; nf++) {
                int r = wn + nf * 8 + g;
                tf32_split(Bs[cur][r][kk + tig    ], bfh[nf][0], bfl[nf][0]);
                tf32_split(Bs[cur][r][kk + tig + 4], bfh[nf][1], bfl[nf][1]);
            }
            #pragma unroll
            for (int mf = 0; mf < 2; mf++)
                #pragma unroll
                for (int nf = 0; nf < 8; nf++) {
                    mma8(c[mf][nf], afh[mf], bfl[nf]);   // hi*lo
                    mma8(c[mf][nf], afl[mf], bfh[nf]);   // lo*hi
                    mma8(c[mf][nf], afh[mf], bfh[nf]);   // hi*hi (last: largest term)
                }
        }
        __syncthreads();
    }
#undef LOADT

    // ---- epilogue: c[mf][nf] = {(g,2tig),(g,2tig+1),(g+8,2tig),(g+8,2tig+1)} ----
    #pragma unroll
    for (int mf = 0; mf < 2; mf++) {
        #pragma unroll
        for (int rh = 0; rh < 2; rh++) {
            int m = m0 + wm + mf * 16 + g + rh * 8;
            if (m >= M) continue;
            #pragma unroll
            for (int nf = 0; nf < 8; nf++) {
                int n = n0 + wn + nf * 8 + 2 * tig;
                float vx = c[mf][nf][rh * 2], vy = c[mf][nf][rh * 2 + 1];
                if (bias) {
                    float2 bb = *(const float2*)&bias[n];
                    vx += bb.x; vy += bb.y;
                }
                if (act == 1) {
                    vx = 1.f / (1.f + expf(-vx));
                    vy = 1.f / (1.f + expf(-vy));
                } else if (act == 2) {
                    vx = 0.5f * vx * (1.f + erff(vx * 0.70710678118654752f));
                    vy = 0.5f * vy * (1.f + erff(vy * 0.70710678118654752f));
                }
                if (res) {
                    float2 rr = *(const float2*)&res[(size_t)m * N + n];
                    vx += rr.x; vy += rr.y;
                }
                float2 v = make_float2(vx, vy);
                *(float2*)&C[(size_t)m * N + n] = v;
            }
        }
    }
}

// ============================================================
// weight transpose [K,N] -> [N,K] (full fp32)
// ============================================================
__global__ void transpose_w(const float* __restrict__ src, float* __restrict__ dst,
                            int K, int N)
{
    __shared__ float t[32][33];
    int nb = blockIdx.x * 32, kb = blockIdx.y * 32;
    int tx = threadIdx.x, ty = threadIdx.y;  // 32x8
    #pragma unroll
    for (int j = 0; j < 32; j += 8)
        t[ty + j][tx] = src[(size_t)(kb + ty + j) * N + nb + tx];
    __syncthreads();
    #pragma unroll
    for (int j = 0; j < 32; j += 8)
        dst[(size_t)(nb + ty + j) * K + kb + tx] = t[tx][ty + j];
}

// ============================================================
// SPT
// ============================================================
__device__ __forceinline__ float ln512(float a, float* red, int tid) {
    red[tid] = a; __syncthreads();
    for (int s = 256; s > 0; s >>= 1) { if (tid < s) red[tid] += red[tid + s]; __syncthreads(); }
    float mu = red[0] * (1.f / 512.f); __syncthreads();
    float dv = a - mu;
    red[tid] = dv * dv; __syncthreads();
    for (int s = 256; s > 0; s >>= 1) { if (tid < s) red[tid] += red[tid + s]; __syncthreads(); }
    float var = red[0] * (1.f / 512.f); __syncthreads();
    return dv * rsqrtf(var + 1e-5f);
}

__global__ void spt_kernel(const float* __restrict__ img,
    const float* __restrict__ w0, const float* __restrict__ bb0,
    const float* __restrict__ gg0, const float* __restrict__ be0,
    const float* __restrict__ w1, const float* __restrict__ bb1,
    const float* __restrict__ gg1, const float* __restrict__ be1,
    float* __restrict__ comb)
{
    int blk = blockIdx.x;
    int b = blk >> 8;
    int p = blk & 255;
    int py = p >> 4, px = p & 15;

    __shared__ float patch[10][10];
    __shared__ float red[512];
    int tid = threadIdx.x;

    if (tid < 100) {
        int r = tid / 10, c = tid % 10;
        int ir = (py * 8 - 1 + r) & 127;
        int ic = (px * 8 - 1 + c) & 127;
        patch[r][c] = img[((size_t)b * IMGS + ir) * IMGS + ic];
    }
    __syncthreads();

    const int dy[5] = {1, 0, 2, 0, 2};
    const int dx[5] = {1, 0, 0, 2, 2};

    int d = tid;
    float a0 = bb0[d], a1 = bb1[d];
    const float* wp0 = w0 + (size_t)d * 320;
    const float* wp1 = w1 + (size_t)d * 320;

    for (int c = 0; c < 5; c++) {
        #pragma unroll
        for (int i = 0; i < 8; i++) {
            #pragma unroll
            for (int j = 0; j < 8; j++) {
                float xv = patch[i + dy[c]][j + dx[c]];
                int wi = (c * 8 + i) * 8 + j;
                a0 = fmaf(wp0[wi], xv, a0);
                a1 = fmaf(wp1[wi], xv, a1);
            }
        }
    }

    float n0 = ln512(a0, red, tid) * gg0[d] + be0[d];
    float n1 = ln512(a1, red, tid) * gg1[d] + be1[d];

    size_t row = blk;
    comb[row * 1024 + d]       = n0;
    comb[row * 1024 + 512 + d] = n1;
}

// ============================================================
// LayerNorm over D=512
// ============================================================
__global__ void ln_kernel(const float* __restrict__ in, const float* __restrict__ g,
                          const float* __restrict__ bta, float* __restrict__ out)
{
    int row = blockIdx.x, tid = threadIdx.x;
    __shared__ float red[128];
    const float* xr = in + (size_t)row * Dm;
    float v[4]; float s = 0.f;
    #pragma unroll
    for (int i = 0; i < 4; i++) { v[i] = xr[tid + 128 * i]; s += v[i]; }
    red[tid] = s; __syncthreads();
    for (int st = 64; st > 0; st >>= 1) { if (tid < st) red[tid] += red[tid + st]; __syncthreads(); }
    float mu = red[0] * (1.f / 512.f); __syncthreads();
    float s2 = 0.f;
    #pragma unroll
    for (int i = 0; i < 4; i++) { float dv = v[i] - mu; s2 += dv * dv; }
    red[tid] = s2; __syncthreads();
    for (int st = 64; st > 0; st >>= 1) { if (tid < st) red[tid] += red[tid + st]; __syncthreads(); }
    float inv = rsqrtf(red[0] * (1.f / 512.f) + 1e-5f);
    float* orow = out + (size_t)row * Dm;
    #pragma unroll
    for (int i = 0; i < 4; i++) {
        int idx = tid + 128 * i;
        orow[idx] = (v[i] - mu) * inv * g[idx] + bta[idx];
    }
}

// ============================================================
// Tiled fused attention (proven at R2)
// ============================================================
#define QTILES 5
#define SS_LD  260
#define ATTN_SMEM ((64*68 + 64*68 + 64*SS_LD) * 4)

__global__ __launch_bounds__(256) void attn_kernel(
    const float* __restrict__ qkv, const float* __restrict__ temp,
    float* __restrict__ o)
{
    extern __shared__ float sm[];
    float* Qs  = sm;
    float* KVs = sm + 64 * 68;
    float* Ss  = sm + 2 * 64 * 68;

    int qt = blockIdx.x, h = blockIdx.y, b = blockIdx.z;
    int tid = threadIdx.x;
    int tx = tid & 15, ty = tid >> 4;

    const size_t base = (size_t)b * NT * 1536 + (size_t)h * 64;

    {
        int dth = (tid & 15) * 4;
        #pragma unroll
        for (int pass = 0; pass < 4; pass++) {
            int q = (tid >> 4) + pass * 16;
            int n = qt * 64 + q; if (n > NT - 1) n = NT - 1;
            float4 v = *(const float4*)&qkv[base + (size_t)n * 1536 + dth];
            Qs[(dth + 0) * 68 + q] = v.x;
            Qs[(dth + 1) * 68 + q] = v.y;
            Qs[(dth + 2) * 68 + q] = v.z;
            Qs[(dth + 3) * 68 + q] = v.w;
        }
    }

    float tmp = temp[h];
    int nbase = qt * 64;

    for (int mc = 0; mc < NT; mc += 64) {
        __syncthreads();
        {
            int dth = (tid & 15) * 4;
            #pragma unroll
            for (int pass = 0; pass < 4; pass++) {
                int m = (tid >> 4) + pass * 16;
                int mg = mc + m; if (mg > NT - 1) mg = NT - 1;
                float4 v = *(const float4*)&qkv[base + 512 + (size_t)mg * 1536 + dth];
                KVs[(dth + 0) * 68 + m] = v.x;
                KVs[(dth + 1) * 68 + m] = v.y;
                KVs[(dth + 2) * 68 + m] = v.z;
                KVs[(dth + 3) * 68 + m] = v.w;
            }
        }
        __syncthreads();

        float acc[4][4] = {};
        #pragma unroll
        for (int kk = 0; kk < 64; kk++) {
            float4 a = *(const float4*)&Qs[kk * 68 + ty * 4];
            float4 bb = *(const float4*)&KVs[kk * 68 + tx * 4];
            float av[4] = {a.x, a.y, a.z, a.w};
            float bv[4] = {bb.x, bb.y, bb.z, bb.w};
            #pragma unroll
            for (int i = 0; i < 4; i++)
                #pragma unroll
                for (int j = 0; j < 4; j++)
                    acc[i][j] = fmaf(av[i], bv[j], acc[i][j]);
        }
        #pragma unroll
        for (int i = 0; i < 4; i++) {
            int q = ty * 4 + i;
            int n = nbase + q;
            #pragma unroll
            for (int j = 0; j < 4; j++) {
                int m = mc + tx * 4 + j;
                if (m < NT) {
                    float s = acc[i][j] * tmp;
                    if (m == n) s = -INFINITY;
                    Ss[q * SS_LD + m] = s;
                }
            }
        }
    }
    __syncthreads();

    {
        int wid = tid >> 5, lane = tid & 31;
        for (int r = 0; r < 8; r++) {
            float* row = Ss + (wid * 8 + r) * SS_LD;
            float mx = -INFINITY;
            for (int m = lane; m < NT; m += 32) mx = fmaxf(mx, row[m]);
            #pragma unroll
            for (int s = 16; s > 0; s >>= 1) mx = fmaxf(mx, __shfl_xor_sync(0xffffffffu, mx, s));
            float sum = 0.f;
            for (int m = lane; m < NT; m += 32) { float e = expf(row[m] - mx); row[m] = e; sum += e; }
            #pragma unroll
            for (int s = 16; s > 0; s >>= 1) sum += __shfl_xor_sync(0xffffffffu, sum, s);
            float inv = 1.f / sum;
            for (int m = lane; m < NT; m += 32) row[m] *= inv;
        }
    }

    float acc[4][4] = {};
    for (int mc = 0; mc < NT; mc += 64) {
        __syncthreads();
        {
            int dth = (tid & 15) * 4;
            #pragma unroll
            for (int pass = 0; pass < 4; pass++) {
                int m = (tid >> 4) + pass * 16;
                int mg = mc + m; if (mg > NT - 1) mg = NT - 1;
                float4 v = *(const float4*)&qkv[base + 1024 + (size_t)mg * 1536 + dth];
                *(float4*)&KVs[m * 68 + dth] = v;
            }
        }
        __syncthreads();
        int mlim = NT - mc; if (mlim > 64) mlim = 64;
        for (int mm = 0; mm < mlim; mm++) {
            float4 bb = *(const float4*)&KVs[mm * 68 + tx * 4];
            float bv[4] = {bb.x, bb.y, bb.z, bb.w};
            #pragma unroll
            for (int i = 0; i < 4; i++) {
                float p = Ss[(ty * 4 + i) * SS_LD + mc + mm];
                #pragma unroll
                for (int j = 0; j < 4; j++)
                    acc[i][j] = fmaf(p, bv[j], acc[i][j]);
            }
        }
    }

    #pragma unroll
    for (int i = 0; i < 4; i++) {
        int n = nbase + ty * 4 + i;
        if (n < NT) {
            float4 v;
            v.x = acc[i][0]; v.y = acc[i][1]; v.z = acc[i][2]; v.w = acc[i][3];
            *(float4*)&o[((size_t)(b * NT + n)) * Dm + h * 64 + tx * 4] = v;
        }
    }
}

// ============================================================
// fuse / cls / head
// ============================================================
__global__ void fuse_kernel(const float* __restrict__ comb, const float* __restrict__ gate,
                            const float* __restrict__ pos, float* __restrict__ tok)
{
    int idx = blockIdx.x * blockDim.x + threadIdx.x;
    if (idx >= Bq * NP * Dm) return;
    int d = idx & 511;
    int row = idx >> 9;
    int b = row >> 8, p = row & 255;
    float g  = gate[idx];
    float sv = comb[(size_t)row * 1024 + d];
    float ov = comb[(size_t)row * 1024 + 512 + d];
    tok[((size_t)(b * NT) + 1 + p) * Dm + d] =
        g * sv + (1.f - g) * ov + pos[(size_t)(1 + p) * Dm + d];
}

__global__ void cls_kernel(const float* __restrict__ cls, const float* __restrict__ pos,
                           float* __restrict__ tok)
{
    int idx = blockIdx.x * blockDim.x + threadIdx.x;
    if (idx >= Bq * Dm) return;
    int d = idx & 511, b = idx >> 9;
    tok[(size_t)b * NT * Dm + d] = cls[d] + pos[d];
}

__global__ void head_kernel(const float* __restrict__ tok, const float* __restrict__ ng,
                            const float* __restrict__ nb, const float* __restrict__ hw,
                            const float* __restrict__ hb, float* __restrict__ out)
{
    int b = blockIdx.x, tid = threadIdx.x;
    __shared__ float red[128];
    const float* xr = tok + (size_t)b * NT * Dm;
    float v[4]; float s = 0.f;
    #pragma unroll
    for (int i = 0; i < 4; i++) { v[i] = xr[tid + 128 * i]; s += v[i]; }
    red[tid] = s; __syncthreads();
    for (int st = 64; st > 0; st >>= 1) { if (tid < st) red[tid] += red[tid + st]; __syncthreads(); }
    float mu = red[0] * (1.f / 512.f); __syncthreads();
    float s2 = 0.f;
    #pragma unroll
    for (int i = 0; i < 4; i++) { float dv = v[i] - mu; s2 += dv * dv; }
    red[tid] = s2; __syncthreads();
    for (int st = 64; st > 0; st >>= 1) { if (tid < st) red[tid] += red[tid + st]; __syncthreads(); }
    float inv = rsqrtf(red[0] * (1.f / 512.f) + 1e-5f);
    __syncthreads();

    float xn[4];
    #pragma unroll
    for (int i = 0; i < 4; i++) {
        int idx = tid + 128 * i;
        xn[i] = (v[i] - mu) * inv * ng[idx] + nb[idx];
    }

    for (int c = 0; c < 3; c++) {
        float p = 0.f;
        #pragma unroll
        for (int i = 0; i < 4; i++) {
            int idx = tid + 128 * i;
            p = fmaf(xn[i], hw[idx * 3 + c], p);
        }
        red[tid] = p; __syncthreads();
        for (int st = 64; st > 0; st >>= 1) { if (tid < st) red[tid] += red[tid + st]; __syncthreads(); }
        if (tid == 0) out[b * 3 + c] = red[0] + hb[c];
        __syncthreads();
    }
}

// ============================================================
// Launch
// ============================================================
static inline void launch_gemm(const float* A, const float* BT, const float* bias,
                               const float* res, float* C, int M, int Nn, int K, int act)
{
    dim3 grid(Nn / 128, (M + 127) / 128);
    mma_gemm<<<grid, 256>>>(A, BT, bias, res, C, M, Nn, K, act);
}

extern "C" void kernel_launch(void* const* d_in, const int* in_sizes, int n_in,
                              void* d_out, int out_size)
{
    const float* image   = (const float*)d_in[0];
    const float* ssw     = (const float*)d_in[1];
    const float* ssb     = (const float*)d_in[2];
    const float* ssg     = (const float*)d_in[3];
    const float* ssbeta  = (const float*)d_in[4];
    const float* sow     = (const float*)d_in[5];
    const float* sob     = (const float*)d_in[6];
    const float* sog     = (const float*)d_in[7];
    const float* sobeta  = (const float*)d_in[8];
    const float* fw      = (const float*)d_in[9];
    const float* fb      = (const float*)d_in[10];
    const float* cls     = (const float*)d_in[11];
    const float* pos     = (const float*)d_in[12];
    const float* ln1g    = (const float*)d_in[13];
    const float* ln1b    = (const float*)d_in[14];
    const float* qkvw    = (const float*)d_in[15];
    const float* qkvb    = (const float*)d_in[16];
    const float* projw   = (const float*)d_in[17];
    const float* projb   = (const float*)d_in[18];
    const float* temp    = (const float*)d_in[19];
    const float* ln2g    = (const float*)d_in[20];
    const float* ln2b    = (const float*)d_in[21];
    const float* w1      = (const float*)d_in[22];
    const float* b1      = (const float*)d_in[23];
    const float* w2      = (const float*)d_in[24];
    const float* b2      = (const float*)d_in[25];
    const float* ng      = (const float*)d_in[26];
    const float* nb      = (const float*)d_in[27];
    const float* hw      = (const float*)d_in[28];
    const float* hb      = (const float*)d_in[29];

    float *comb, *gate, *tok, *x, *qkv, *o, *h, *wT;
    cudaGetSymbolAddress((void**)&comb, g_comb);
    cudaGetSymbolAddress((void**)&gate, g_gate);
    cudaGetSymbolAddress((void**)&tok,  g_tok);
    cudaGetSymbolAddress((void**)&x,    g_x);
    cudaGetSymbolAddress((void**)&qkv,  g_qkv);
    cudaGetSymbolAddress((void**)&o,    g_o);
    cudaGetSymbolAddress((void**)&h,    g_h);
    cudaGetSymbolAddress((void**)&wT,   g_wT);

    cudaFuncSetAttribute(attn_kernel, cudaFuncAttributeMaxDynamicSharedMemorySize, ATTN_SMEM);

    const int Mtok = Bq * NT;   // 8224
    const int Mpat = Bq * NP;   // 8192

    // ---- weight transposes (fp32) ----
    transpose_w<<<dim3(512 / 32, 1024 / 32), dim3(32, 8)>>>(fw, wT + FWT_OFF, 1024, 512);
    for (int l = 0; l < NL; l++) {
        float* lb = wT + LAYER_OFF(l);
        transpose_w<<<dim3(1536 / 32, 512 / 32), dim3(32, 8)>>>(qkvw + (size_t)l * 512 * 1536, lb + QKVT_OFF, 512, 1536);
        transpose_w<<<dim3(512 / 32, 512 / 32), dim3(32, 8)>>>(projw + (size_t)l * 512 * 512, lb + PROJT_OFF, 512, 512);
        transpose_w<<<dim3(2048 / 32, 512 / 32), dim3(32, 8)>>>(w1 + (size_t)l * 512 * 2048, lb + W1T_OFF, 512, 2048);
        transpose_w<<<dim3(512 / 32, 2048 / 32), dim3(32, 8)>>>(w2 + (size_t)l * 2048 * 512, lb + W2T_OFF, 2048, 512);
    }

    // ---- front end ----
    spt_kernel<<<Mpat, 512>>>(image, ssw, ssb, ssg, ssbeta,
                              sow, sob, sog, sobeta, comb);
    launch_gemm(comb, wT + FWT_OFF, fb, nullptr, gate, Mpat, Dm, 2 * Dm, /*sigmoid*/1);
    fuse_kernel<<<(Mpat * Dm + 255) / 256, 256>>>(comb, gate, pos, tok);
    cls_kernel<<<(Bq * Dm + 255) / 256, 256>>>(cls, pos, tok);

    // ---- transformer layers ----
    for (int l = 0; l < NL; l++) {
        float* lb = wT + LAYER_OFF(l);
        ln_kernel<<<Mtok, 128>>>(tok, ln1g + l * Dm, ln1b + l * Dm, x);
        launch_gemm(x, lb + QKVT_OFF, qkvb + l * 3 * Dm, nullptr, qkv, Mtok, 3 * Dm, Dm, 0);
        attn_kernel<<<dim3(QTILES, NH, Bq), 256, ATTN_SMEM>>>(qkv, temp + l * NH, o);
        launch_gemm(o, lb + PROJT_OFF, projb + l * Dm, tok, tok, Mtok, Dm, Dm, 0);
        ln_kernel<<<Mtok, 128>>>(tok, ln2g + l * Dm, ln2b + l * Dm, x);
        launch_gemm(x, lb + W1T_OFF, b1 + l * MLPD, nullptr, h, Mtok, MLPD, Dm, /*gelu*/2);
        launch_gemm(h, lb + W2T_OFF, b2 + l * Dm, tok, tok, Mtok, Dm, MLPD, 0);
    }

    // ---- head ----
    head_kernel<<<Bq, 128>>>(tok, ng, nb, hw, hb, (float*)d_out);
}